// round 12
// baseline (speedup 1.0000x reference)
#include <cuda_runtime.h>
#include <cuda_bf16.h>
#include <math.h>
#include <stdint.h>

#define N_NODES   20000
#define N_EDGES   320000
#define NUM_GRAPHS 64
#define D0 256   // input dim
#define D1 256   // hidden 1
#define D2 128   // hidden 2

// ---------------- device scratch (static globals; no runtime alloc) ----------------
__device__ __align__(16) int   g_deg[N_NODES];
__device__ __align__(16) int   g_csr_off[N_NODES + 1];
__device__ __align__(16) int   g_csr_cur[N_NODES];
__device__ __align__(16) int2  g_edge[N_EDGES];              // {src, dinv[src] bits}
__device__ __align__(16) float g_dinv[N_NODES];
__device__ __align__(16) __nv_bfloat16 g_h1[(size_t)N_NODES * D1];  // X@W1 (bf16)
__device__ __align__(16) float g_z1[(size_t)N_NODES * D1];          // relu(agg1+b1) fp32
__device__ __align__(16) __nv_bfloat16 g_h2[(size_t)N_NODES * D2];  // Z1@W2 (bf16)
__device__ __align__(16) float g_gsum[NUM_GRAPHS * D2];
__device__ __align__(16) int   g_gcnt[NUM_GRAPHS];

// ---------------- init ----------------
__global__ void init_kernel() {
    int i = blockIdx.x * blockDim.x + threadIdx.x;
    int stride = gridDim.x * blockDim.x;
    for (int k = i; k < N_NODES; k += stride) g_deg[k] = 0;
    for (int k = i; k < NUM_GRAPHS * D2; k += stride) g_gsum[k] = 0.0f;
    if (i < NUM_GRAPHS) g_gcnt[i] = 0;
}

// ---------------- degree histogram over dst, 4 edges/thread ----------------
__global__ void count_kernel(const int* __restrict__ ei) {
    int i = blockIdx.x * blockDim.x + threadIdx.x;
    if (i < N_EDGES / 4) {
        int4 d = __ldg(reinterpret_cast<const int4*>(ei + N_EDGES) + i);
        atomicAdd(&g_deg[d.x], 1);
        atomicAdd(&g_deg[d.y], 1);
        atomicAdd(&g_deg[d.z], 1);
        atomicAdd(&g_deg[d.w], 1);
    }
}

// ---------------- single-block warp-shuffle scan ----------------
__global__ void scan_kernel() {
    __shared__ int warp_sums[32];
    int tid = threadIdx.x;            // 1024 threads
    int lane = tid & 31, wid = tid >> 5;
    int carry = 0;
    for (int base = 0; base < N_NODES; base += 1024) {
        int i = base + tid;
        int v = (i < N_NODES) ? g_deg[i] : 0;
        int x = v;
        #pragma unroll
        for (int off = 1; off < 32; off <<= 1) {
            int y = __shfl_up_sync(0xffffffffu, x, off);
            if (lane >= off) x += y;
        }
        if (lane == 31) warp_sums[wid] = x;
        __syncthreads();
        if (wid == 0) {
            int w = warp_sums[lane];
            #pragma unroll
            for (int off = 1; off < 32; off <<= 1) {
                int y = __shfl_up_sync(0xffffffffu, w, off);
                if (lane >= off) w += y;
            }
            warp_sums[lane] = w;
        }
        __syncthreads();
        int warp_prefix = (wid > 0) ? warp_sums[wid - 1] : 0;
        int incl = carry + warp_prefix + x;
        if (i < N_NODES) {
            g_csr_off[i + 1] = incl;
            g_csr_cur[i]     = incl - v;
            g_dinv[i]        = rsqrtf((float)(v + 1));
        }
        if (i == 0) g_csr_off[0] = 0;
        int tot = warp_sums[31];
        __syncthreads();
        carry += tot;
    }
}

// ---------------- CSR fill: 4 edges/thread, packed {src, w} per slot ----------------
__global__ void fill_kernel(const int* __restrict__ ei) {
    int i = blockIdx.x * blockDim.x + threadIdx.x;
    if (i < N_EDGES / 4) {
        int4 s4 = __ldg(reinterpret_cast<const int4*>(ei) + i);
        int4 d4 = __ldg(reinterpret_cast<const int4*>(ei + N_EDGES) + i);
        int slot;
        slot = atomicAdd(&g_csr_cur[d4.x], 1);
        g_edge[slot] = make_int2(s4.x, __float_as_int(g_dinv[s4.x]));
        slot = atomicAdd(&g_csr_cur[d4.y], 1);
        g_edge[slot] = make_int2(s4.y, __float_as_int(g_dinv[s4.y]));
        slot = atomicAdd(&g_csr_cur[d4.z], 1);
        g_edge[slot] = make_int2(s4.z, __float_as_int(g_dinv[s4.z]));
        slot = atomicAdd(&g_csr_cur[d4.w], 1);
        g_edge[slot] = make_int2(s4.w, __float_as_int(g_dinv[s4.w]));
    }
}

// ============ bf16 tensor-core GEMM (mma.sync m16n8k16): C(bf16) = A(f32) @ B(f32) ============
#define BM 128
#define BN 128
#define ASTR 20   // As word stride: A-frag LDS conflict-free, v4 STS aligned
#define BSTR 21   // Bs word stride: transpose STS conflict-free

__global__ __launch_bounds__(256, 2)
void gemm_bf16_kernel(const float* __restrict__ A, const float* __restrict__ B,
                      __nv_bfloat16* __restrict__ C, int M, int N, int K) {
    __shared__ uint32_t As[BM * ASTR];   // [row][k2] bf16x2, k2 = 0..15
    __shared__ uint32_t Bs[BN * BSTR];   // [col][k2] bf16x2 (transposed)

    int tid  = threadIdx.x;              // 256
    int lane = tid & 31, wid = tid >> 5; // 8 warps
    int wm = wid & 1, wn = wid >> 1;     // warp grid 2(M) x 4(N)
    int warp_row = wm * 64;
    int warp_col = wn * 32;
    int row0 = blockIdx.x * BM;
    int col0 = blockIdx.y * BN;
    int tig = lane & 3, grp = lane >> 2;

    float acc[4][4][4] = {};             // [mt][nt][reg]

    for (int k0 = 0; k0 < K; k0 += 32) {
        // ---- A chunk: 128 rows x 32 cols fp32 -> bf16x2
        #pragma unroll
        for (int i = 0; i < 2; i++) {
            int idx = tid + (i << 8);
            int r  = idx >> 2;            // 0..127
            int c8 = (idx & 3) << 3;      // 0,8,16,24
            int gr = row0 + r;
            float4 v0 = make_float4(0.f,0.f,0.f,0.f), v1 = v0;
            if (gr < M) {
                const float4* ap = reinterpret_cast<const float4*>(&A[(size_t)gr * K + k0 + c8]);
                v0 = ap[0]; v1 = ap[1];
            }
            __nv_bfloat162 p0 = __float22bfloat162_rn(make_float2(v0.x, v0.y));
            __nv_bfloat162 p1 = __float22bfloat162_rn(make_float2(v0.z, v0.w));
            __nv_bfloat162 p2 = __float22bfloat162_rn(make_float2(v1.x, v1.y));
            __nv_bfloat162 p3 = __float22bfloat162_rn(make_float2(v1.z, v1.w));
            uint32_t* dst = &As[r * ASTR + (c8 >> 1)];
            *reinterpret_cast<uint4*>(dst) =
                make_uint4(*reinterpret_cast<uint32_t*>(&p0), *reinterpret_cast<uint32_t*>(&p1),
                           *reinterpret_cast<uint32_t*>(&p2), *reinterpret_cast<uint32_t*>(&p3));
        }
        // ---- B chunk transposed: Bs[n][k2] = {B[k0+2k2][n], B[k0+2k2+1][n]}
        #pragma unroll
        for (int i = 0; i < 8; i++) {
            int idx = tid + (i << 8);     // 0..2047
            int k2 = idx >> 7;            // 0..15
            int n  = idx & 127;
            const float* bp = &B[(size_t)(k0 + 2 * k2) * N + col0 + n];
            float f0 = bp[0];
            float f1 = bp[N];
            __nv_bfloat162 p = __float22bfloat162_rn(make_float2(f0, f1));
            Bs[n * BSTR + k2] = *reinterpret_cast<uint32_t*>(&p);
        }
        __syncthreads();

        #pragma unroll
        for (int ks = 0; ks < 2; ks++) {  // two k16 steps per chunk
            int kw = ks << 3;             // word offset 0 or 8
            uint32_t af[4][4], bf[4][2];
            #pragma unroll
            for (int mt = 0; mt < 4; mt++) {
                int r = warp_row + mt * 16 + grp;
                af[mt][0] = As[r * ASTR + kw + tig];
                af[mt][1] = As[(r + 8) * ASTR + kw + tig];
                af[mt][2] = As[r * ASTR + kw + tig + 4];
                af[mt][3] = As[(r + 8) * ASTR + kw + tig + 4];
            }
            #pragma unroll
            for (int nt = 0; nt < 4; nt++) {
                int c = warp_col + nt * 8 + grp;
                bf[nt][0] = Bs[c * BSTR + kw + tig];
                bf[nt][1] = Bs[c * BSTR + kw + tig + 4];
            }
            #pragma unroll
            for (int mt = 0; mt < 4; mt++)
                #pragma unroll
                for (int nt = 0; nt < 4; nt++) {
                    asm volatile(
                        "mma.sync.aligned.m16n8k16.row.col.f32.bf16.bf16.f32 "
                        "{%0,%1,%2,%3}, {%4,%5,%6,%7}, {%8,%9}, {%0,%1,%2,%3};\n"
                        : "+f"(acc[mt][nt][0]), "+f"(acc[mt][nt][1]),
                          "+f"(acc[mt][nt][2]), "+f"(acc[mt][nt][3])
                        : "r"(af[mt][0]), "r"(af[mt][1]), "r"(af[mt][2]), "r"(af[mt][3]),
                          "r"(bf[nt][0]), "r"(bf[nt][1]));
                }
        }
        __syncthreads();
    }

    // epilogue: bf16x2 packed stores; c0/c1 at (row, 2*tig), c2/c3 at (row+8, 2*tig)
    #pragma unroll
    for (int mt = 0; mt < 4; mt++) {
        int r_lo = row0 + warp_row + mt * 16 + grp;
        int r_hi = r_lo + 8;
        #pragma unroll
        for (int nt = 0; nt < 4; nt++) {
            int c = col0 + warp_col + nt * 8 + 2 * tig;
            if (r_lo < M) {
                __nv_bfloat162 p = __float22bfloat162_rn(make_float2(acc[mt][nt][0], acc[mt][nt][1]));
                *reinterpret_cast<uint32_t*>(&C[(size_t)r_lo * N + c]) = *reinterpret_cast<uint32_t*>(&p);
            }
            if (r_hi < M) {
                __nv_bfloat162 p = __float22bfloat162_rn(make_float2(acc[mt][nt][2], acc[mt][nt][3]));
                *reinterpret_cast<uint32_t*>(&C[(size_t)r_hi * N + c]) = *reinterpret_cast<uint32_t*>(&p);
            }
        }
    }
}

// ---------------- gather aggregation (bf16 gathers, 8 feats/thread) ----------------
__device__ __forceinline__ void bf8_fma(uint4 u, float w, float* acc) {
    float2 f;
    f = __bfloat1622float2(*reinterpret_cast<__nv_bfloat162*>(&u.x));
    acc[0] = fmaf(w, f.x, acc[0]); acc[1] = fmaf(w, f.y, acc[1]);
    f = __bfloat1622float2(*reinterpret_cast<__nv_bfloat162*>(&u.y));
    acc[2] = fmaf(w, f.x, acc[2]); acc[3] = fmaf(w, f.y, acc[3]);
    f = __bfloat1622float2(*reinterpret_cast<__nv_bfloat162*>(&u.z));
    acc[4] = fmaf(w, f.x, acc[4]); acc[5] = fmaf(w, f.y, acc[5]);
    f = __bfloat1622float2(*reinterpret_cast<__nv_bfloat162*>(&u.w));
    acc[6] = fmaf(w, f.x, acc[6]); acc[7] = fmaf(w, f.y, acc[7]);
}

template <int F, bool POOL>
__global__ void aggregate_kernel(const __nv_bfloat16* __restrict__ H, const float* __restrict__ bias,
                                 float* __restrict__ Z, const int* __restrict__ batch) {
    constexpr int TF  = F / 8;          // threads per node (uint4 = 8 bf16)
    constexpr int NPB = 256 / TF;
    int node = blockIdx.x * NPB + threadIdx.y;
    if (node >= N_NODES) return;
    int t = threadIdx.x;                // 0..TF-1
    const uint4* H4 = reinterpret_cast<const uint4*>(H);

    float di = g_dinv[node];
    float acc[8] = {};
    bf8_fma(__ldg(&H4[(size_t)node * TF + t]), di, acc);

    int e = g_csr_off[node], e1 = g_csr_off[node + 1];
    for (; e + 1 < e1; e += 2) {
        int2 r0 = __ldg(&g_edge[e]);
        int2 r1 = __ldg(&g_edge[e + 1]);
        uint4 u0 = __ldg(&H4[(size_t)r0.x * TF + t]);
        uint4 u1 = __ldg(&H4[(size_t)r1.x * TF + t]);
        bf8_fma(u0, __int_as_float(r0.y), acc);
        bf8_fma(u1, __int_as_float(r1.y), acc);
    }
    if (e < e1) {
        int2 r0 = __ldg(&g_edge[e]);
        bf8_fma(__ldg(&H4[(size_t)r0.x * TF + t]), __int_as_float(r0.y), acc);
    }

    const float4* b4 = reinterpret_cast<const float4*>(bias) + 2 * t;
    float4 bl = __ldg(b4), bh = __ldg(b4 + 1);
    float v[8];
    v[0] = fmaxf(fmaf(di, acc[0], bl.x), 0.0f);
    v[1] = fmaxf(fmaf(di, acc[1], bl.y), 0.0f);
    v[2] = fmaxf(fmaf(di, acc[2], bl.z), 0.0f);
    v[3] = fmaxf(fmaf(di, acc[3], bl.w), 0.0f);
    v[4] = fmaxf(fmaf(di, acc[4], bh.x), 0.0f);
    v[5] = fmaxf(fmaf(di, acc[5], bh.y), 0.0f);
    v[6] = fmaxf(fmaf(di, acc[6], bh.z), 0.0f);
    v[7] = fmaxf(fmaf(di, acc[7], bh.w), 0.0f);

    if (POOL) {
        int g = batch[node];
        float* gp = &g_gsum[g * F + 8 * t];
        #pragma unroll
        for (int i = 0; i < 8; i++) atomicAdd(gp + i, v[i]);
        if (t == 0) atomicAdd(&g_gcnt[g], 1);
    } else {
        float4* zp = reinterpret_cast<float4*>(&Z[(size_t)node * F + 8 * t]);
        zp[0] = make_float4(v[0], v[1], v[2], v[3]);
        zp[1] = make_float4(v[4], v[5], v[6], v[7]);
    }
}

// ---------------- head MLP ----------------
__global__ void final_kernel(const float* __restrict__ Wl1, const float* __restrict__ bl1,
                             const float* __restrict__ Wl2, const float* __restrict__ bl2,
                             float* __restrict__ out) {
    int g = blockIdx.x;
    int j = threadIdx.x;    // 64
    __shared__ float sg[D2];
    __shared__ float sr[64];
    float cnt = (float)max(g_gcnt[g], 1);
    for (int k = j; k < D2; k += 64) sg[k] = g_gsum[g * D2 + k] / cnt;
    __syncthreads();
    float acc = bl1[j];
    #pragma unroll 8
    for (int k = 0; k < D2; k++) acc = fmaf(sg[k], Wl1[k * 64 + j], acc);
    acc = fmaxf(acc, 0.0f);
    sr[j] = acc * Wl2[j];
    #pragma unroll
    for (int off = 32; off > 0; off >>= 1) {
        __syncthreads();
        if (j < off) sr[j] += sr[j + off];
    }
    __syncthreads();
    if (j == 0) out[g] = 1.0f / (1.0f + expf(-(sr[0] + bl2[0])));
}

// ---------------- launch ----------------
extern "C" void kernel_launch(void* const* d_in, const int* in_sizes, int n_in,
                              void* d_out, int out_size) {
    const float* x     = (const float*)d_in[0];
    const int*   ei    = (const int*)d_in[1];     // int32 (JAX x64 disabled)
    const int*   batch = (const int*)d_in[2];     // int32
    const float* W1  = (const float*)d_in[3];
    const float* b1  = (const float*)d_in[4];
    const float* W2  = (const float*)d_in[5];
    const float* b2  = (const float*)d_in[6];
    const float* Wl1 = (const float*)d_in[7];
    const float* bl1 = (const float*)d_in[8];
    const float* Wl2 = (const float*)d_in[9];
    const float* bl2 = (const float*)d_in[10];
    float* out = (float*)d_out;

    void* p;
    cudaGetSymbolAddress(&p, g_h1); __nv_bfloat16* h1 = (__nv_bfloat16*)p;
    cudaGetSymbolAddress(&p, g_z1); float* z1 = (float*)p;
    cudaGetSymbolAddress(&p, g_h2); __nv_bfloat16* h2 = (__nv_bfloat16*)p;

    init_kernel<<<64, 256>>>();
    count_kernel<<<(N_EDGES / 4 + 255) / 256, 256>>>(ei);
    scan_kernel<<<1, 1024>>>();
    fill_kernel<<<(N_EDGES / 4 + 255) / 256, 256>>>(ei);

    dim3 gg1((N_NODES + BM - 1) / BM, D1 / BN);   // (157, 2)
    gemm_bf16_kernel<<<gg1, 256>>>(x, W1, h1, N_NODES, D1, D0);
    {
        dim3 blk(D1 / 8, 256 / (D1 / 8));         // (32, 8)
        aggregate_kernel<D1, false><<<(N_NODES + 7) / 8, blk>>>(h1, b1, z1, nullptr);
    }

    dim3 gg2((N_NODES + BM - 1) / BM, D2 / BN);   // (157, 1)
    gemm_bf16_kernel<<<gg2, 256>>>(z1, W2, h2, N_NODES, D2, D1);
    {
        dim3 blk(D2 / 8, 256 / (D2 / 8));         // (16, 16)
        aggregate_kernel<D2, true><<<(N_NODES + 15) / 16, blk>>>(h2, b2, nullptr, batch);
    }

    final_kernel<<<NUM_GRAPHS, 64>>>(Wl1, bl1, Wl2, bl2, out);
}

// round 13
// speedup vs baseline: 1.1556x; 1.1556x over previous
#include <cuda_runtime.h>
#include <cuda_bf16.h>
#include <math.h>
#include <stdint.h>

#define N_NODES   20000
#define N_EDGES   320000
#define NUM_GRAPHS 64
#define D0 256   // input dim
#define D1 256   // hidden 1
#define D2 128   // hidden 2

// ---------------- device scratch (static globals; no runtime alloc) ----------------
__device__ __align__(16) int   g_deg[N_NODES];
__device__ __align__(16) int   g_csr_off[N_NODES + 1];
__device__ __align__(16) int   g_csr_cur[N_NODES];
__device__ __align__(16) int2  g_edge[N_EDGES];              // {src, dinv[src] bits}
__device__ __align__(16) float g_dinv[N_NODES];
__device__ __align__(16) float g_h1[(size_t)N_NODES * D1];
__device__ __align__(16) float g_z1[(size_t)N_NODES * D1];
__device__ __align__(16) float g_h2[(size_t)N_NODES * D2];
__device__ __align__(16) float g_gsum[NUM_GRAPHS * D2];
__device__ __align__(16) int   g_gcnt[NUM_GRAPHS];

// ---------------- init ----------------
__global__ void init_kernel() {
    int i = blockIdx.x * blockDim.x + threadIdx.x;
    int stride = gridDim.x * blockDim.x;
    for (int k = i; k < N_NODES; k += stride) g_deg[k] = 0;
    for (int k = i; k < NUM_GRAPHS * D2; k += stride) g_gsum[k] = 0.0f;
    if (i < NUM_GRAPHS) g_gcnt[i] = 0;
}

// ---------------- degree histogram over dst, 4 edges/thread ----------------
__global__ void count_kernel(const int* __restrict__ ei) {
    int i = blockIdx.x * blockDim.x + threadIdx.x;
    if (i < N_EDGES / 4) {
        int4 d = __ldg(reinterpret_cast<const int4*>(ei + N_EDGES) + i);
        atomicAdd(&g_deg[d.x], 1);
        atomicAdd(&g_deg[d.y], 1);
        atomicAdd(&g_deg[d.z], 1);
        atomicAdd(&g_deg[d.w], 1);
    }
}

// ---------------- single-block warp-shuffle scan ----------------
__global__ void scan_kernel() {
    __shared__ int warp_sums[32];
    int tid = threadIdx.x;            // 1024 threads
    int lane = tid & 31, wid = tid >> 5;
    int carry = 0;
    for (int base = 0; base < N_NODES; base += 1024) {
        int i = base + tid;
        int v = (i < N_NODES) ? g_deg[i] : 0;
        int x = v;
        #pragma unroll
        for (int off = 1; off < 32; off <<= 1) {
            int y = __shfl_up_sync(0xffffffffu, x, off);
            if (lane >= off) x += y;
        }
        if (lane == 31) warp_sums[wid] = x;
        __syncthreads();
        if (wid == 0) {
            int w = warp_sums[lane];
            #pragma unroll
            for (int off = 1; off < 32; off <<= 1) {
                int y = __shfl_up_sync(0xffffffffu, w, off);
                if (lane >= off) w += y;
            }
            warp_sums[lane] = w;
        }
        __syncthreads();
        int warp_prefix = (wid > 0) ? warp_sums[wid - 1] : 0;
        int incl = carry + warp_prefix + x;
        if (i < N_NODES) {
            g_csr_off[i + 1] = incl;
            g_csr_cur[i]     = incl - v;
            g_dinv[i]        = rsqrtf((float)(v + 1));
        }
        if (i == 0) g_csr_off[0] = 0;
        int tot = warp_sums[31];
        __syncthreads();
        carry += tot;
    }
}

// ---------------- CSR fill: 4 edges/thread, packed {src, w} per slot ----------------
__global__ void fill_kernel(const int* __restrict__ ei) {
    int i = blockIdx.x * blockDim.x + threadIdx.x;
    if (i < N_EDGES / 4) {
        int4 s4 = __ldg(reinterpret_cast<const int4*>(ei) + i);
        int4 d4 = __ldg(reinterpret_cast<const int4*>(ei + N_EDGES) + i);
        int slot;
        slot = atomicAdd(&g_csr_cur[d4.x], 1);
        g_edge[slot] = make_int2(s4.x, __float_as_int(g_dinv[s4.x]));
        slot = atomicAdd(&g_csr_cur[d4.y], 1);
        g_edge[slot] = make_int2(s4.y, __float_as_int(g_dinv[s4.y]));
        slot = atomicAdd(&g_csr_cur[d4.z], 1);
        g_edge[slot] = make_int2(s4.z, __float_as_int(g_dinv[s4.z]));
        slot = atomicAdd(&g_csr_cur[d4.w], 1);
        g_edge[slot] = make_int2(s4.w, __float_as_int(g_dinv[s4.w]));
    }
}

// ============ bf16 tensor-core GEMM (mma.sync m16n8k16): C(f32) = A(f32) @ B(f32) ============
#define BM 128
#define BN 128
#define ASTR 20   // As word stride: A-frag LDS conflict-free, v4 STS aligned
#define BSTR 21   // Bs word stride: transpose STS conflict-free

__global__ __launch_bounds__(256, 2)
void gemm_bf16_kernel(const float* __restrict__ A, const float* __restrict__ B,
                      float* __restrict__ C, int M, int N, int K) {
    __shared__ uint32_t As[BM * ASTR];   // [row][k2] bf16x2, k2 = 0..15
    __shared__ uint32_t Bs[BN * BSTR];   // [col][k2] bf16x2 (transposed)

    int tid  = threadIdx.x;              // 256
    int lane = tid & 31, wid = tid >> 5; // 8 warps
    int wm = wid & 1, wn = wid >> 1;     // warp grid 2(M) x 4(N)
    int warp_row = wm * 64;
    int warp_col = wn * 32;
    int row0 = blockIdx.x * BM;
    int col0 = blockIdx.y * BN;
    int tig = lane & 3, grp = lane >> 2;

    float acc[4][4][4] = {};             // [mt][nt][reg]

    for (int k0 = 0; k0 < K; k0 += 32) {
        // ---- A chunk: 128 rows x 32 cols fp32 -> bf16x2
        #pragma unroll
        for (int i = 0; i < 2; i++) {
            int idx = tid + (i << 8);
            int r  = idx >> 2;            // 0..127
            int c8 = (idx & 3) << 3;      // 0,8,16,24
            int gr = row0 + r;
            float4 v0 = make_float4(0.f,0.f,0.f,0.f), v1 = v0;
            if (gr < M) {
                const float4* ap = reinterpret_cast<const float4*>(&A[(size_t)gr * K + k0 + c8]);
                v0 = ap[0]; v1 = ap[1];
            }
            __nv_bfloat162 p0 = __float22bfloat162_rn(make_float2(v0.x, v0.y));
            __nv_bfloat162 p1 = __float22bfloat162_rn(make_float2(v0.z, v0.w));
            __nv_bfloat162 p2 = __float22bfloat162_rn(make_float2(v1.x, v1.y));
            __nv_bfloat162 p3 = __float22bfloat162_rn(make_float2(v1.z, v1.w));
            uint32_t* dst = &As[r * ASTR + (c8 >> 1)];
            *reinterpret_cast<uint4*>(dst) =
                make_uint4(*reinterpret_cast<uint32_t*>(&p0), *reinterpret_cast<uint32_t*>(&p1),
                           *reinterpret_cast<uint32_t*>(&p2), *reinterpret_cast<uint32_t*>(&p3));
        }
        // ---- B chunk transposed: Bs[n][k2] = {B[k0+2k2][n], B[k0+2k2+1][n]}
        #pragma unroll
        for (int i = 0; i < 8; i++) {
            int idx = tid + (i << 8);     // 0..2047
            int k2 = idx >> 7;            // 0..15
            int n  = idx & 127;
            const float* bp = &B[(size_t)(k0 + 2 * k2) * N + col0 + n];
            float f0 = bp[0];
            float f1 = bp[N];
            __nv_bfloat162 p = __float22bfloat162_rn(make_float2(f0, f1));
            Bs[n * BSTR + k2] = *reinterpret_cast<uint32_t*>(&p);
        }
        __syncthreads();

        #pragma unroll
        for (int ks = 0; ks < 2; ks++) {  // two k16 steps per chunk
            int kw = ks << 3;             // word offset 0 or 8
            uint32_t af[4][4], bf[4][2];
            #pragma unroll
            for (int mt = 0; mt < 4; mt++) {
                int r = warp_row + mt * 16 + grp;
                af[mt][0] = As[r * ASTR + kw + tig];
                af[mt][1] = As[(r + 8) * ASTR + kw + tig];
                af[mt][2] = As[r * ASTR + kw + tig + 4];
                af[mt][3] = As[(r + 8) * ASTR + kw + tig + 4];
            }
            #pragma unroll
            for (int nt = 0; nt < 4; nt++) {
                int c = warp_col + nt * 8 + grp;
                bf[nt][0] = Bs[c * BSTR + kw + tig];
                bf[nt][1] = Bs[c * BSTR + kw + tig + 4];
            }
            #pragma unroll
            for (int mt = 0; mt < 4; mt++)
                #pragma unroll
                for (int nt = 0; nt < 4; nt++) {
                    asm volatile(
                        "mma.sync.aligned.m16n8k16.row.col.f32.bf16.bf16.f32 "
                        "{%0,%1,%2,%3}, {%4,%5,%6,%7}, {%8,%9}, {%0,%1,%2,%3};\n"
                        : "+f"(acc[mt][nt][0]), "+f"(acc[mt][nt][1]),
                          "+f"(acc[mt][nt][2]), "+f"(acc[mt][nt][3])
                        : "r"(af[mt][0]), "r"(af[mt][1]), "r"(af[mt][2]), "r"(af[mt][3]),
                          "r"(bf[nt][0]), "r"(bf[nt][1]));
                }
        }
        __syncthreads();
    }

    // epilogue: c0/c1 at (row, 2*tig), c2/c3 at (row+8, 2*tig)
    #pragma unroll
    for (int mt = 0; mt < 4; mt++) {
        int r_lo = row0 + warp_row + mt * 16 + grp;
        int r_hi = r_lo + 8;
        #pragma unroll
        for (int nt = 0; nt < 4; nt++) {
            int c = col0 + warp_col + nt * 8 + 2 * tig;
            if (r_lo < M) {
                float2 v = make_float2(acc[mt][nt][0], acc[mt][nt][1]);
                *reinterpret_cast<float2*>(&C[(size_t)r_lo * N + c]) = v;
            }
            if (r_hi < M) {
                float2 v = make_float2(acc[mt][nt][2], acc[mt][nt][3]);
                *reinterpret_cast<float2*>(&C[(size_t)r_hi * N + c]) = v;
            }
        }
    }
}

// ---------------- gather aggregation (float4, packed edges, unroll-2) ----------------
template <int F, bool POOL>
__global__ void aggregate_kernel(const float* __restrict__ H, const float* __restrict__ bias,
                                 float* __restrict__ Z, const int* __restrict__ batch) {
    constexpr int TF  = F / 4;
    constexpr int NPB = 256 / TF;
    int node = blockIdx.x * NPB + threadIdx.y;
    if (node >= N_NODES) return;
    int t = threadIdx.x;
    const float4* H4 = reinterpret_cast<const float4*>(H);

    float di = g_dinv[node];
    float4 h = __ldg(&H4[(size_t)node * TF + t]);
    float4 acc = make_float4(di * h.x, di * h.y, di * h.z, di * h.w);

    int e = g_csr_off[node], e1 = g_csr_off[node + 1];
    for (; e + 1 < e1; e += 2) {
        int2 r0 = __ldg(&g_edge[e]);
        int2 r1 = __ldg(&g_edge[e + 1]);
        float4 h0 = __ldg(&H4[(size_t)r0.x * TF + t]);
        float4 h1 = __ldg(&H4[(size_t)r1.x * TF + t]);
        float w0 = __int_as_float(r0.y), w1 = __int_as_float(r1.y);
        acc.x = fmaf(w0, h0.x, fmaf(w1, h1.x, acc.x));
        acc.y = fmaf(w0, h0.y, fmaf(w1, h1.y, acc.y));
        acc.z = fmaf(w0, h0.z, fmaf(w1, h1.z, acc.z));
        acc.w = fmaf(w0, h0.w, fmaf(w1, h1.w, acc.w));
    }
    if (e < e1) {
        int2 r0 = __ldg(&g_edge[e]);
        float4 h0 = __ldg(&H4[(size_t)r0.x * TF + t]);
        float w0 = __int_as_float(r0.y);
        acc.x = fmaf(w0, h0.x, acc.x);
        acc.y = fmaf(w0, h0.y, acc.y);
        acc.z = fmaf(w0, h0.z, acc.z);
        acc.w = fmaf(w0, h0.w, acc.w);
    }
    float4 b4 = __ldg(&reinterpret_cast<const float4*>(bias)[t]);
    float4 v;
    v.x = fmaxf(fmaf(di, acc.x, b4.x), 0.0f);
    v.y = fmaxf(fmaf(di, acc.y, b4.y), 0.0f);
    v.z = fmaxf(fmaf(di, acc.z, b4.z), 0.0f);
    v.w = fmaxf(fmaf(di, acc.w, b4.w), 0.0f);

    if (POOL) {
        int g = batch[node];
        float* gp = &g_gsum[g * F + 4 * t];
        atomicAdd(gp + 0, v.x);
        atomicAdd(gp + 1, v.y);
        atomicAdd(gp + 2, v.z);
        atomicAdd(gp + 3, v.w);
        if (t == 0) atomicAdd(&g_gcnt[g], 1);
    } else {
        reinterpret_cast<float4*>(Z)[(size_t)node * TF + t] = v;
    }
}

// ---------------- head MLP ----------------
__global__ void final_kernel(const float* __restrict__ Wl1, const float* __restrict__ bl1,
                             const float* __restrict__ Wl2, const float* __restrict__ bl2,
                             float* __restrict__ out) {
    int g = blockIdx.x;
    int j = threadIdx.x;    // 64
    __shared__ float sg[D2];
    __shared__ float sr[64];
    float cnt = (float)max(g_gcnt[g], 1);
    for (int k = j; k < D2; k += 64) sg[k] = g_gsum[g * D2 + k] / cnt;
    __syncthreads();
    float acc = bl1[j];
    #pragma unroll 8
    for (int k = 0; k < D2; k++) acc = fmaf(sg[k], Wl1[k * 64 + j], acc);
    acc = fmaxf(acc, 0.0f);
    sr[j] = acc * Wl2[j];
    #pragma unroll
    for (int off = 32; off > 0; off >>= 1) {
        __syncthreads();
        if (j < off) sr[j] += sr[j + off];
    }
    __syncthreads();
    if (j == 0) out[g] = 1.0f / (1.0f + expf(-(sr[0] + bl2[0])));
}

// ---------------- launch: fork CSR build || GEMM1, join before agg1 ----------------
extern "C" void kernel_launch(void* const* d_in, const int* in_sizes, int n_in,
                              void* d_out, int out_size) {
    const float* x     = (const float*)d_in[0];
    const int*   ei    = (const int*)d_in[1];     // int32 (JAX x64 disabled)
    const int*   batch = (const int*)d_in[2];     // int32
    const float* W1  = (const float*)d_in[3];
    const float* b1  = (const float*)d_in[4];
    const float* W2  = (const float*)d_in[5];
    const float* b2  = (const float*)d_in[6];
    const float* Wl1 = (const float*)d_in[7];
    const float* bl1 = (const float*)d_in[8];
    const float* Wl2 = (const float*)d_in[9];
    const float* bl2 = (const float*)d_in[10];
    float* out = (float*)d_out;

    void* p;
    cudaGetSymbolAddress(&p, g_h1); float* h1 = (float*)p;
    cudaGetSymbolAddress(&p, g_z1); float* z1 = (float*)p;
    cudaGetSymbolAddress(&p, g_h2); float* h2 = (float*)p;

    // lazy-init side stream + fork/join events (created on the eager correctness
    // call; capture sees only event-record/wait nodes — graph-legal)
    static cudaStream_t s1 = nullptr;
    static cudaEvent_t evFork = nullptr, evJoin = nullptr;
    if (s1 == nullptr) {
        cudaStreamCreateWithFlags(&s1, cudaStreamNonBlocking);
        cudaEventCreateWithFlags(&evFork, cudaEventDisableTiming);
        cudaEventCreateWithFlags(&evJoin, cudaEventDisableTiming);
    }

    // fork: CSR build chain on s1, GEMM1 on main stream (independent work)
    cudaEventRecord(evFork, 0);
    cudaStreamWaitEvent(s1, evFork, 0);

    init_kernel<<<64, 256, 0, s1>>>();
    count_kernel<<<(N_EDGES / 4 + 255) / 256, 256, 0, s1>>>(ei);
    scan_kernel<<<1, 1024, 0, s1>>>();
    fill_kernel<<<(N_EDGES / 4 + 255) / 256, 256, 0, s1>>>(ei);

    dim3 gg1((N_NODES + BM - 1) / BM, D1 / BN);   // (157, 2)
    gemm_bf16_kernel<<<gg1, 256>>>(x, W1, h1, N_NODES, D1, D0);

    // join: agg1 needs both CSR and h1
    cudaEventRecord(evJoin, s1);
    cudaStreamWaitEvent(0, evJoin, 0);

    {
        dim3 blk(D1 / 4, 256 / (D1 / 4));         // (64, 4)
        aggregate_kernel<D1, false><<<(N_NODES + 3) / 4, blk>>>(h1, b1, z1, nullptr);
    }

    dim3 gg2((N_NODES + BM - 1) / BM, D2 / BN);   // (157, 1)
    gemm_bf16_kernel<<<gg2, 256>>>(z1, W2, h2, N_NODES, D2, D1);
    {
        dim3 blk(D2 / 4, 256 / (D2 / 4));         // (32, 8)
        aggregate_kernel<D2, true><<<(N_NODES + 7) / 8, blk>>>(h2, b2, nullptr, batch);
    }

    final_kernel<<<NUM_GRAPHS, 64>>>(Wl1, bl1, Wl2, bl2, out);
}